// round 1
// baseline (speedup 1.0000x reference)
#include <cuda_runtime.h>
#include <cstdint>

#define N_NODES 100000
#define OUT_STRIDE 352   // 128 + 128 + 64 + 32

// Scratch for neighbor aggregation (max layer dim = 128).
__device__ float g_hn[(size_t)N_NODES * 128];

// ---------------------------------------------------------------------------
// zero kernel (h_n init)
// ---------------------------------------------------------------------------
__global__ void zero_kernel(int n_f4) {
    int i = blockIdx.x * blockDim.x + threadIdx.x;
    if (i < n_f4) {
        ((float4*)g_hn)[i] = make_float4(0.f, 0.f, 0.f, 0.f);
    }
}

// ---------------------------------------------------------------------------
// copy x -> out[:, 0:128]
// ---------------------------------------------------------------------------
__global__ void copy_x_kernel(const float* __restrict__ x, float* __restrict__ out, int n) {
    int i = blockIdx.x * blockDim.x + threadIdx.x;   // one float4 per thread
    int node = i >> 5;       // 128/4 = 32 float4 per row
    int c = (i & 31) * 4;
    if (node < n) {
        float4 v = *(const float4*)(x + (size_t)node * 128 + c);
        *(float4*)(out + (size_t)node * OUT_STRIDE + c) = v;
    }
}

// ---------------------------------------------------------------------------
// Edge scatter: g_hn[dst] += attn * x[src]   (float4 vector RED, no return)
// ---------------------------------------------------------------------------
template <int D>
__global__ void scatter_kernel(const float* __restrict__ x, int xs,
                               const int* __restrict__ src,
                               const int* __restrict__ dst,
                               const float* __restrict__ attn, int E) {
    constexpr int C = D / 4;   // float4 chunks per row
    int i = blockIdx.x * blockDim.x + threadIdx.x;
    int e = i / C;
    if (e >= E) return;
    int c = (i % C) * 4;
    int s = __ldg(src + e);
    int d = __ldg(dst + e);
    float a = __ldg(attn + e);
    float4 v = *(const float4*)(x + (size_t)s * xs + c);
    float* p = g_hn + (size_t)d * D + c;
    asm volatile("red.global.add.v4.f32 [%0], {%1, %2, %3, %4};"
                 :: "l"(p), "f"(v.x * a), "f"(v.y * a), "f"(v.z * a), "f"(v.w * a)
                 : "memory");
}

// ---------------------------------------------------------------------------
// Fused bi-interaction layer:
//   out[:, off:off+OUT] = lrelu((x+hn)@W1 + b1) + lrelu((x*hn)@W2 + b2)
// Register-blocked tiled GEMM: 256 threads, each computes a 4x4 (node x col)
// micro-tile with separate accumulators for the W1 and W2 paths.
// ---------------------------------------------------------------------------
__device__ __forceinline__ float lrelu(float v) { return fmaxf(v, 0.01f * v); }

template <int IN, int OUT>
__global__ void fuse_kernel(const float* __restrict__ xin, int xs,
                            const float* __restrict__ W1, const float* __restrict__ b1,
                            const float* __restrict__ W2, const float* __restrict__ b2,
                            float* __restrict__ out, int off, int N) {
    constexpr int BN = 4096 / OUT;  // nodes per block (32 / 64 / 128)
    constexpr int KT = 32;          // k tile
    constexpr int CG = OUT / 4;     // col groups

    __shared__ float s_tile[KT][BN + 4];
    __shared__ float p_tile[KT][BN + 4];
    __shared__ float w1_t[KT][OUT];
    __shared__ float w2_t[KT][OUT];

    int tid = threadIdx.x;
    int n0 = blockIdx.x * BN;
    int cg = tid % CG;       // this thread's col group (cols cg*4 .. +3)
    int ng = tid / CG;       // node group (nodes ng*4 .. +3 within tile)

    float acc1[4][4];
    float acc2[4][4];
#pragma unroll
    for (int i = 0; i < 4; i++)
#pragma unroll
        for (int j = 0; j < 4; j++) { acc1[i][j] = 0.f; acc2[i][j] = 0.f; }

    for (int k0 = 0; k0 < IN; k0 += KT) {
        __syncthreads();
        // load s = x + hn, p = x * hn  (transposed into [k][node])
        for (int idx = tid; idx < BN * (KT / 4); idx += 256) {
            int node = idx / (KT / 4);
            int kq = (idx % (KT / 4)) * 4;
            int gn = n0 + node;
            float4 xv = make_float4(0.f, 0.f, 0.f, 0.f);
            float4 hv = xv;
            if (gn < N) {
                xv = *(const float4*)(xin + (size_t)gn * xs + k0 + kq);
                hv = *(const float4*)(g_hn + (size_t)gn * IN + k0 + kq);
            }
            s_tile[kq + 0][node] = xv.x + hv.x;  p_tile[kq + 0][node] = xv.x * hv.x;
            s_tile[kq + 1][node] = xv.y + hv.y;  p_tile[kq + 1][node] = xv.y * hv.y;
            s_tile[kq + 2][node] = xv.z + hv.z;  p_tile[kq + 2][node] = xv.z * hv.z;
            s_tile[kq + 3][node] = xv.w + hv.w;  p_tile[kq + 3][node] = xv.w * hv.w;
        }
        // load W tiles (contiguous rows [k0:k0+KT, :])
        for (int idx = tid; idx < KT * OUT / 4; idx += 256) {
            ((float4*)w1_t)[idx] = *(const float4*)(W1 + (size_t)k0 * OUT + idx * 4);
            ((float4*)w2_t)[idx] = *(const float4*)(W2 + (size_t)k0 * OUT + idx * 4);
        }
        __syncthreads();

#pragma unroll 8
        for (int k = 0; k < KT; k++) {
            float4 sv = *(const float4*)&s_tile[k][ng * 4];
            float4 pv = *(const float4*)&p_tile[k][ng * 4];
            float4 w1v = *(const float4*)&w1_t[k][cg * 4];
            float4 w2v = *(const float4*)&w2_t[k][cg * 4];
            float sa[4] = {sv.x, sv.y, sv.z, sv.w};
            float pa[4] = {pv.x, pv.y, pv.z, pv.w};
            float wa[4] = {w1v.x, w1v.y, w1v.z, w1v.w};
            float wb[4] = {w2v.x, w2v.y, w2v.z, w2v.w};
#pragma unroll
            for (int i = 0; i < 4; i++)
#pragma unroll
                for (int j = 0; j < 4; j++) {
                    acc1[i][j] = fmaf(sa[i], wa[j], acc1[i][j]);
                    acc2[i][j] = fmaf(pa[i], wb[j], acc2[i][j]);
                }
        }
    }

    float4 b1v = *(const float4*)(b1 + cg * 4);
    float4 b2v = *(const float4*)(b2 + cg * 4);
    float bb1[4] = {b1v.x, b1v.y, b1v.z, b1v.w};
    float bb2[4] = {b2v.x, b2v.y, b2v.z, b2v.w};
#pragma unroll
    for (int i = 0; i < 4; i++) {
        int gn = n0 + ng * 4 + i;
        if (gn >= N) continue;
        float4 o;
        o.x = lrelu(acc1[i][0] + bb1[0]) + lrelu(acc2[i][0] + bb2[0]);
        o.y = lrelu(acc1[i][1] + bb1[1]) + lrelu(acc2[i][1] + bb2[1]);
        o.z = lrelu(acc1[i][2] + bb1[2]) + lrelu(acc2[i][2] + bb2[2]);
        o.w = lrelu(acc1[i][3] + bb1[3]) + lrelu(acc2[i][3] + bb2[3]);
        *(float4*)(out + (size_t)gn * OUT_STRIDE + off + cg * 4) = o;
    }
}

// ---------------------------------------------------------------------------
extern "C" void kernel_launch(void* const* d_in, const int* in_sizes, int n_in,
                              void* d_out, int out_size) {
    const float* x    = (const float*)d_in[0];
    const int*   src  = (const int*)d_in[1];
    const int*   dst  = (const int*)d_in[2];
    const float* attn = (const float*)d_in[3];
    const float* W1_0 = (const float*)d_in[4];
    const float* b1_0 = (const float*)d_in[5];
    const float* W2_0 = (const float*)d_in[6];
    const float* b2_0 = (const float*)d_in[7];
    const float* W1_1 = (const float*)d_in[8];
    const float* b1_1 = (const float*)d_in[9];
    const float* W2_1 = (const float*)d_in[10];
    const float* b2_1 = (const float*)d_in[11];
    const float* W1_2 = (const float*)d_in[12];
    const float* b1_2 = (const float*)d_in[13];
    const float* W2_2 = (const float*)d_in[14];
    const float* b2_2 = (const float*)d_in[15];
    float* out = (float*)d_out;

    int N = in_sizes[0] / 128;
    int E = in_sizes[1];

    // out[:, 0:128] = x
    {
        int threads = N * 32;
        copy_x_kernel<<<(threads + 255) / 256, 256>>>(x, out, N);
    }

    // ---- layer 0: IN=128, OUT=128, input = x (stride 128), out off 128 ----
    {
        int nz = N * 128 / 4;
        zero_kernel<<<(nz + 255) / 256, 256>>>(nz);
        int t = E * 32;
        scatter_kernel<128><<<(t + 255) / 256, 256>>>(x, 128, src, dst, attn, E);
        fuse_kernel<128, 128><<<(N + 31) / 32, 256>>>(x, 128, W1_0, b1_0, W2_0, b2_0, out, 128, N);
    }

    // ---- layer 1: IN=128, OUT=64, input = out[:,128:] (stride 352), off 256 ----
    {
        int nz = N * 128 / 4;
        zero_kernel<<<(nz + 255) / 256, 256>>>(nz);
        int t = E * 32;
        scatter_kernel<128><<<(t + 255) / 256, 256>>>(out + 128, OUT_STRIDE, src, dst, attn, E);
        fuse_kernel<128, 64><<<(N + 63) / 64, 256>>>(out + 128, OUT_STRIDE, W1_1, b1_1, W2_1, b2_1, out, 256, N);
    }

    // ---- layer 2: IN=64, OUT=32, input = out[:,256:] (stride 352), off 320 ----
    {
        int nz = N * 64 / 4;
        zero_kernel<<<(nz + 255) / 256, 256>>>(nz);
        int t = E * 16;
        scatter_kernel<64><<<(t + 255) / 256, 256>>>(out + 256, OUT_STRIDE, src, dst, attn, E);
        fuse_kernel<64, 32><<<(N + 127) / 128, 256>>>(out + 256, OUT_STRIDE, W1_2, b1_2, W2_2, b2_2, out, 320, N);
    }
}

// round 3
// speedup vs baseline: 1.5522x; 1.5522x over previous
#include <cuda_runtime.h>
#include <cstdint>

#define N_NODES 100000
#define N_EDGES_MAX 3200000
#define OUT_STRIDE 352   // 128 + 128 + 64 + 32

// Scratch (static __device__ globals per allocation rules)
__device__ float g_hn[(size_t)N_NODES * 128];
__device__ int   g_deg[N_NODES];
__device__ int   g_rowstart[N_NODES + 1];
__device__ int   g_cursor[N_NODES];
__device__ int2  g_edges[N_EDGES_MAX];   // {src, bitcast(attn)} sorted by dst

// ---------------------------------------------------------------------------
// CSR build
// ---------------------------------------------------------------------------
__global__ void zero_deg_kernel(int n) {
    int i = blockIdx.x * blockDim.x + threadIdx.x;
    if (i < n) g_deg[i] = 0;
}

__global__ void hist_kernel(const int* __restrict__ dst, int E) {
    int e = blockIdx.x * blockDim.x + threadIdx.x;
    if (e < E) atomicAdd(&g_deg[dst[e]], 1);
}

// single-block chunked exclusive scan: g_deg -> g_rowstart, g_cursor
__global__ void scan_kernel(int n) {
    __shared__ int partial[1024];
    int tid = threadIdx.x;
    int chunk = (n + 1023) / 1024;
    int start = tid * chunk;
    int end = min(start + chunk, n);
    int s = 0;
    for (int i = start; i < end; i++) s += g_deg[i];
    partial[tid] = s;
    __syncthreads();
    // Hillis-Steele inclusive scan
    for (int off = 1; off < 1024; off <<= 1) {
        int v = (tid >= off) ? partial[tid - off] : 0;
        __syncthreads();
        partial[tid] += v;
        __syncthreads();
    }
    int base = (tid == 0) ? 0 : partial[tid - 1];
    for (int i = start; i < end; i++) {
        g_rowstart[i] = base;
        g_cursor[i]   = base;
        base += g_deg[i];
    }
    if (tid == 0) g_rowstart[n] = partial[1023];
}

__global__ void fill_kernel(const int* __restrict__ src,
                            const int* __restrict__ dst,
                            const float* __restrict__ attn, int E) {
    int e = blockIdx.x * blockDim.x + threadIdx.x;
    if (e >= E) return;
    int d = dst[e];
    int pos = atomicAdd(&g_cursor[d], 1);
    g_edges[pos] = make_int2(src[e], __float_as_int(attn[e]));
}

// ---------------------------------------------------------------------------
// copy x -> out[:, 0:128]
// ---------------------------------------------------------------------------
__global__ void copy_x_kernel(const float* __restrict__ x, float* __restrict__ out, int n) {
    int i = blockIdx.x * blockDim.x + threadIdx.x;   // one float4 per thread
    int node = i >> 5;
    int c = (i & 31) * 4;
    if (node < n) {
        float4 v = *(const float4*)(x + (size_t)node * 128 + c);
        *(float4*)(out + (size_t)node * OUT_STRIDE + c) = v;
    }
}

// ---------------------------------------------------------------------------
// CSR aggregation: one warp per node.
//   g_hn[v] = sum_{e in row v} attn_e * x[src_e]
// D=128: each lane owns a float4 column slice. D=64: float2.
// ---------------------------------------------------------------------------
template <int D>
__global__ void agg_kernel(const float* __restrict__ x, int xs, int N) {
    int warp = (blockIdx.x * blockDim.x + threadIdx.x) >> 5;
    int lane = threadIdx.x & 31;
    if (warp >= N) return;
    int beg = g_rowstart[warp];
    int end = g_rowstart[warp + 1];

    if (D == 128) {
        float4 acc = make_float4(0.f, 0.f, 0.f, 0.f);
        int i = beg;
        // unroll-2 for MLP
        for (; i + 1 < end; i += 2) {
            int2 e0 = __ldg(&g_edges[i]);
            int2 e1 = __ldg(&g_edges[i + 1]);
            float a0 = __int_as_float(e0.y);
            float a1 = __int_as_float(e1.y);
            float4 v0 = __ldg((const float4*)(x + (size_t)e0.x * xs + lane * 4));
            float4 v1 = __ldg((const float4*)(x + (size_t)e1.x * xs + lane * 4));
            acc.x = fmaf(a0, v0.x, acc.x); acc.y = fmaf(a0, v0.y, acc.y);
            acc.z = fmaf(a0, v0.z, acc.z); acc.w = fmaf(a0, v0.w, acc.w);
            acc.x = fmaf(a1, v1.x, acc.x); acc.y = fmaf(a1, v1.y, acc.y);
            acc.z = fmaf(a1, v1.z, acc.z); acc.w = fmaf(a1, v1.w, acc.w);
        }
        if (i < end) {
            int2 e0 = __ldg(&g_edges[i]);
            float a0 = __int_as_float(e0.y);
            float4 v0 = __ldg((const float4*)(x + (size_t)e0.x * xs + lane * 4));
            acc.x = fmaf(a0, v0.x, acc.x); acc.y = fmaf(a0, v0.y, acc.y);
            acc.z = fmaf(a0, v0.z, acc.z); acc.w = fmaf(a0, v0.w, acc.w);
        }
        *(float4*)(g_hn + (size_t)warp * 128 + lane * 4) = acc;
    } else {  // D == 64
        float2 acc = make_float2(0.f, 0.f);
        int i = beg;
        for (; i + 1 < end; i += 2) {
            int2 e0 = __ldg(&g_edges[i]);
            int2 e1 = __ldg(&g_edges[i + 1]);
            float a0 = __int_as_float(e0.y);
            float a1 = __int_as_float(e1.y);
            float2 v0 = __ldg((const float2*)(x + (size_t)e0.x * xs + lane * 2));
            float2 v1 = __ldg((const float2*)(x + (size_t)e1.x * xs + lane * 2));
            acc.x = fmaf(a0, v0.x, acc.x); acc.y = fmaf(a0, v0.y, acc.y);
            acc.x = fmaf(a1, v1.x, acc.x); acc.y = fmaf(a1, v1.y, acc.y);
        }
        if (i < end) {
            int2 e0 = __ldg(&g_edges[i]);
            float a0 = __int_as_float(e0.y);
            float2 v0 = __ldg((const float2*)(x + (size_t)e0.x * xs + lane * 2));
            acc.x = fmaf(a0, v0.x, acc.x); acc.y = fmaf(a0, v0.y, acc.y);
        }
        *(float2*)(g_hn + (size_t)warp * 64 + lane * 2) = acc;
    }
}

// ---------------------------------------------------------------------------
// Fused bi-interaction layer (unchanged from R1; at FFMA roofline)
// ---------------------------------------------------------------------------
__device__ __forceinline__ float lrelu(float v) { return fmaxf(v, 0.01f * v); }

template <int IN, int OUT>
__global__ void fuse_kernel(const float* __restrict__ xin, int xs,
                            const float* __restrict__ W1, const float* __restrict__ b1,
                            const float* __restrict__ W2, const float* __restrict__ b2,
                            float* __restrict__ out, int off, int N) {
    constexpr int BN = 4096 / OUT;
    constexpr int KT = 32;
    constexpr int CG = OUT / 4;

    __shared__ float s_tile[KT][BN + 4];
    __shared__ float p_tile[KT][BN + 4];
    __shared__ float w1_t[KT][OUT];
    __shared__ float w2_t[KT][OUT];

    int tid = threadIdx.x;
    int n0 = blockIdx.x * BN;
    int cg = tid % CG;
    int ng = tid / CG;

    float acc1[4][4];
    float acc2[4][4];
#pragma unroll
    for (int i = 0; i < 4; i++)
#pragma unroll
        for (int j = 0; j < 4; j++) { acc1[i][j] = 0.f; acc2[i][j] = 0.f; }

    for (int k0 = 0; k0 < IN; k0 += KT) {
        __syncthreads();
        for (int idx = tid; idx < BN * (KT / 4); idx += 256) {
            int node = idx / (KT / 4);
            int kq = (idx % (KT / 4)) * 4;
            int gn = n0 + node;
            float4 xv = make_float4(0.f, 0.f, 0.f, 0.f);
            float4 hv = xv;
            if (gn < N) {
                xv = *(const float4*)(xin + (size_t)gn * xs + k0 + kq);
                hv = *(const float4*)(g_hn + (size_t)gn * IN + k0 + kq);
            }
            s_tile[kq + 0][node] = xv.x + hv.x;  p_tile[kq + 0][node] = xv.x * hv.x;
            s_tile[kq + 1][node] = xv.y + hv.y;  p_tile[kq + 1][node] = xv.y * hv.y;
            s_tile[kq + 2][node] = xv.z + hv.z;  p_tile[kq + 2][node] = xv.z * hv.z;
            s_tile[kq + 3][node] = xv.w + hv.w;  p_tile[kq + 3][node] = xv.w * hv.w;
        }
        for (int idx = tid; idx < KT * OUT / 4; idx += 256) {
            ((float4*)w1_t)[idx] = *(const float4*)(W1 + (size_t)k0 * OUT + idx * 4);
            ((float4*)w2_t)[idx] = *(const float4*)(W2 + (size_t)k0 * OUT + idx * 4);
        }
        __syncthreads();

#pragma unroll 8
        for (int k = 0; k < KT; k++) {
            float4 sv = *(const float4*)&s_tile[k][ng * 4];
            float4 pv = *(const float4*)&p_tile[k][ng * 4];
            float4 w1v = *(const float4*)&w1_t[k][cg * 4];
            float4 w2v = *(const float4*)&w2_t[k][cg * 4];
            float sa[4] = {sv.x, sv.y, sv.z, sv.w};
            float pa[4] = {pv.x, pv.y, pv.z, pv.w};
            float wa[4] = {w1v.x, w1v.y, w1v.z, w1v.w};
            float wb[4] = {w2v.x, w2v.y, w2v.z, w2v.w};
#pragma unroll
            for (int i = 0; i < 4; i++)
#pragma unroll
                for (int j = 0; j < 4; j++) {
                    acc1[i][j] = fmaf(sa[i], wa[j], acc1[i][j]);
                    acc2[i][j] = fmaf(pa[i], wb[j], acc2[i][j]);
                }
        }
    }

    float4 b1v = *(const float4*)(b1 + cg * 4);
    float4 b2v = *(const float4*)(b2 + cg * 4);
    float bb1[4] = {b1v.x, b1v.y, b1v.z, b1v.w};
    float bb2[4] = {b2v.x, b2v.y, b2v.z, b2v.w};
#pragma unroll
    for (int i = 0; i < 4; i++) {
        int gn = n0 + ng * 4 + i;
        if (gn >= N) continue;
        float4 o;
        o.x = lrelu(acc1[i][0] + bb1[0]) + lrelu(acc2[i][0] + bb2[0]);
        o.y = lrelu(acc1[i][1] + bb1[1]) + lrelu(acc2[i][1] + bb2[1]);
        o.z = lrelu(acc1[i][2] + bb1[2]) + lrelu(acc2[i][2] + bb2[2]);
        o.w = lrelu(acc1[i][3] + bb1[3]) + lrelu(acc2[i][3] + bb2[3]);
        *(float4*)(out + (size_t)gn * OUT_STRIDE + off + cg * 4) = o;
    }
}

// ---------------------------------------------------------------------------
extern "C" void kernel_launch(void* const* d_in, const int* in_sizes, int n_in,
                              void* d_out, int out_size) {
    const float* x    = (const float*)d_in[0];
    const int*   src  = (const int*)d_in[1];
    const int*   dst  = (const int*)d_in[2];
    const float* attn = (const float*)d_in[3];
    const float* W1_0 = (const float*)d_in[4];
    const float* b1_0 = (const float*)d_in[5];
    const float* W2_0 = (const float*)d_in[6];
    const float* b2_0 = (const float*)d_in[7];
    const float* W1_1 = (const float*)d_in[8];
    const float* b1_1 = (const float*)d_in[9];
    const float* W2_1 = (const float*)d_in[10];
    const float* b2_1 = (const float*)d_in[11];
    const float* W1_2 = (const float*)d_in[12];
    const float* b1_2 = (const float*)d_in[13];
    const float* W2_2 = (const float*)d_in[14];
    const float* b2_2 = (const float*)d_in[15];
    float* out = (float*)d_out;

    int N = in_sizes[0] / 128;
    int E = in_sizes[1];

    // ---- CSR build (graph is launch-invariant; built fresh every launch) ----
    zero_deg_kernel<<<(N + 255) / 256, 256>>>(N);
    hist_kernel<<<(E + 255) / 256, 256>>>(dst, E);
    scan_kernel<<<1, 1024>>>(N);
    fill_kernel<<<(E + 255) / 256, 256>>>(src, dst, attn, E);

    // out[:, 0:128] = x
    copy_x_kernel<<<(N * 32 + 255) / 256, 256>>>(x, out, N);

    int agg_blocks = (N + 7) / 8;   // 8 warps per 256-thread block

    // ---- layer 0: IN=128, OUT=128 ----
    agg_kernel<128><<<agg_blocks, 256>>>(x, 128, N);
    fuse_kernel<128, 128><<<(N + 31) / 32, 256>>>(x, 128, W1_0, b1_0, W2_0, b2_0, out, 128, N);

    // ---- layer 1: IN=128, OUT=64, input = out[:,128:256] ----
    agg_kernel<128><<<agg_blocks, 256>>>(out + 128, OUT_STRIDE, N);
    fuse_kernel<128, 64><<<(N + 63) / 64, 256>>>(out + 128, OUT_STRIDE, W1_1, b1_1, W2_1, b2_1, out, 256, N);

    // ---- layer 2: IN=64, OUT=32, input = out[:,256:320] ----
    agg_kernel<64><<<agg_blocks, 256>>>(out + 256, OUT_STRIDE, N);
    fuse_kernel<64, 32><<<(N + 127) / 128, 256>>>(out + 256, OUT_STRIDE, W1_2, b1_2, W2_2, b2_2, out, 320, N);
}